// round 6
// baseline (speedup 1.0000x reference)
#include <cuda_runtime.h>

// PLIF scan: x [B=16, T=16, C=128, H=32, W=32] fp32, scalar leak w.
//   mem = w*mem + x_t; spike = (mem >= 1); mem *= (1 - spike)
//
// Round 6: single balanced wave, cleanly this time.
//   - 2 float4 lanes per thread, both bodies fully inlined (no serializing
//     loop like R4), PLAIN loads/stores (no cache hints — R3 proved __ldcs
//     forces 16-deep batching -> regs 78 -> occ crash; that, not LPT=2,
//     likely killed R2).
//   - __launch_bounds__(256, 8) caps regs at 32: ptxas rebalances its
//     software-pipeline depth under the budget instead of spilling.
//   - Grid = 1024 CTAs x 256 = exactly one resident wave (8 CTAs/SM x 148
//     SMs >= 1024), every CTA identical work -> no wave-quantization tail.

#define B_    16
#define T_    16
#define CHW4  32768                  // (128*32*32)/4 float4 per (b,t) plane
#define NV4   (B_ * CHW4)            // 524288 float4 lanes
#define TPB   256
#define NBLK  1024                   // NV4 / (2 * TPB)
#define NTHR  (NBLK * TPB)           // 262144 threads, 2 lanes each

__device__ __forceinline__ void plif_lane(const float4* __restrict__ x,
                                          float4* __restrict__ out,
                                          int lane, float w)
{
    const int b = lane >> 15;                 // lane / CHW4
    const int s = lane & (CHW4 - 1);          // lane % CHW4
    const float4* xb = x   + (size_t)b * (T_ * CHW4) + s;
    float4*       ob = out + (size_t)b * (T_ * CHW4) + s;

    float4 xs[T_];
    #pragma unroll
    for (int t = 0; t < T_; ++t)
        xs[t] = xb[t * CHW4];

    float m0 = 0.f, m1 = 0.f, m2 = 0.f, m3 = 0.f;

    #pragma unroll
    for (int t = 0; t < T_; ++t) {
        m0 = fmaf(w, m0, xs[t].x);
        m1 = fmaf(w, m1, xs[t].y);
        m2 = fmaf(w, m2, xs[t].z);
        m3 = fmaf(w, m3, xs[t].w);

        const float s0 = (m0 >= 1.0f) ? 1.0f : 0.0f;
        const float s1 = (m1 >= 1.0f) ? 1.0f : 0.0f;
        const float s2 = (m2 >= 1.0f) ? 1.0f : 0.0f;
        const float s3 = (m3 >= 1.0f) ? 1.0f : 0.0f;

        m0 = (s0 != 0.0f) ? 0.0f : m0;
        m1 = (s1 != 0.0f) ? 0.0f : m1;
        m2 = (s2 != 0.0f) ? 0.0f : m2;
        m3 = (s3 != 0.0f) ? 0.0f : m3;

        float4 o; o.x = s0; o.y = s1; o.z = s2; o.w = s3;
        ob[t * CHW4] = o;
    }
}

__global__ __launch_bounds__(TPB, 8) void plif_kernel(
    const float4* __restrict__ x,
    const float*  __restrict__ wp,
    float4*       __restrict__ out)
{
    const int tid = blockIdx.x * blockDim.x + threadIdx.x;
    const float w = *wp;                      // scalar, L1-broadcast

    // Lane pair (tid, tid+NTHR): both fully coalesced across the warp.
    plif_lane(x, out, tid, w);
    plif_lane(x, out, tid + NTHR, w);
}

extern "C" void kernel_launch(void* const* d_in, const int* in_sizes, int n_in,
                              void* d_out, int out_size)
{
    const float4* x  = (const float4*)d_in[0];
    const float*  wp = (const float*)d_in[1];
    float4* out = (float4*)d_out;

    plif_kernel<<<NBLK, TPB>>>(x, wp, out);
}

// round 7
// speedup vs baseline: 1.0862x; 1.0862x over previous
#include <cuda_runtime.h>

// PLIF scan: x [B=16, T=16, C=128, H=32, W=32] fp32, scalar leak w.
//   mem = w*mem + x_t; spike = (mem >= 1); mem *= (1 - spike)
//
// Round 7: R1 winning recipe (1 float4 lane per thread, plain ld/st so
// ptxas picks its preferred pipeline depth at ~31 regs / occ ~80%) with
// TPB=128 -> 4096 CTAs. Same threads/SM, same wave count (1.73), but
// half-size CTA quanta smooth the tail-wave finish skew across SMs.
// (Refuted across R2-R6: cache hints (reg explosion), LPT=2 in any form
// (pipeline-depth halving), single-wave grids (cost > tail savings).)

#define B_   16
#define T_   16
#define CHW4 32768                 // (128*32*32)/4 float4 per (b,t) plane
#define NV4  (B_ * CHW4)           // 524288 float4 lanes
#define TPB  128

__global__ __launch_bounds__(TPB) void plif_kernel(
    const float4* __restrict__ x,
    const float*  __restrict__ wp,
    float4*       __restrict__ out)
{
    const int tid = blockIdx.x * blockDim.x + threadIdx.x;
    if (tid >= NV4) return;

    const float w = *wp;                     // scalar, L1-broadcast

    const int b = tid >> 15;                 // tid / CHW4
    const int s = tid & (CHW4 - 1);          // tid % CHW4
    const float4* xb = x   + (size_t)b * (T_ * CHW4) + s;
    float4*       ob = out + (size_t)b * (T_ * CHW4) + s;

    // Plain loads: ptxas software-pipelines to its preferred depth.
    float4 xs[T_];
    #pragma unroll
    for (int t = 0; t < T_; ++t)
        xs[t] = xb[t * CHW4];

    float m0 = 0.f, m1 = 0.f, m2 = 0.f, m3 = 0.f;

    #pragma unroll
    for (int t = 0; t < T_; ++t) {
        m0 = fmaf(w, m0, xs[t].x);
        m1 = fmaf(w, m1, xs[t].y);
        m2 = fmaf(w, m2, xs[t].z);
        m3 = fmaf(w, m3, xs[t].w);

        const float s0 = (m0 >= 1.0f) ? 1.0f : 0.0f;
        const float s1 = (m1 >= 1.0f) ? 1.0f : 0.0f;
        const float s2 = (m2 >= 1.0f) ? 1.0f : 0.0f;
        const float s3 = (m3 >= 1.0f) ? 1.0f : 0.0f;

        m0 = (s0 != 0.0f) ? 0.0f : m0;
        m1 = (s1 != 0.0f) ? 0.0f : m1;
        m2 = (s2 != 0.0f) ? 0.0f : m2;
        m3 = (s3 != 0.0f) ? 0.0f : m3;

        float4 o; o.x = s0; o.y = s1; o.z = s2; o.w = s3;
        ob[t * CHW4] = o;
    }
}

extern "C" void kernel_launch(void* const* d_in, const int* in_sizes, int n_in,
                              void* d_out, int out_size)
{
    const float4* x  = (const float4*)d_in[0];
    const float*  wp = (const float*)d_in[1];
    float4* out = (float4*)d_out;

    const int blocks = (NV4 + TPB - 1) / TPB;   // 4096
    plif_kernel<<<blocks, TPB>>>(x, wp, out);
}

// round 8
// speedup vs baseline: 1.0870x; 1.0007x over previous
#include <cuda_runtime.h>

// PLIF scan: x [B=16, T=16, C=128, H=32, W=32] fp32, scalar leak w.
//   mem = w*mem + x_t; spike = (mem >= 1); mem *= (1 - spike)
//
// Round 8: 2-phase burst grouping. Per thread: load timesteps 0..7 (8
// back-to-back LDG.128 = same-direction read burst), compute + store 0..7
// (write burst), then the same for 8..15. Groups DRAM accesses into long
// same-direction runs to cut read/write bus-turnaround frequency — the
// hypothesized source of the remaining ~12% gap to spec bandwidth.
// Register cost ~48 (8 float4 payload + state) keeps occ ~60%, which R2
// showed is still bandwidth-sufficient (R2 hit 5.5TB/s at occ 21%).

#define B_    16
#define T_    16
#define HALF  8
#define CHW4  32768                 // (128*32*32)/4 float4 per (b,t) plane
#define NV4   (B_ * CHW4)           // 524288 float4 lanes
#define TPB   256

__global__ __launch_bounds__(TPB) void plif_kernel(
    const float4* __restrict__ x,
    const float*  __restrict__ wp,
    float4*       __restrict__ out)
{
    const int tid = blockIdx.x * blockDim.x + threadIdx.x;
    if (tid >= NV4) return;

    const float w = *wp;                     // scalar, L1-broadcast

    const int b = tid >> 15;                 // tid / CHW4
    const int s = tid & (CHW4 - 1);          // tid % CHW4
    const float4* xb = x   + (size_t)b * (T_ * CHW4) + s;
    float4*       ob = out + (size_t)b * (T_ * CHW4) + s;

    float m0 = 0.f, m1 = 0.f, m2 = 0.f, m3 = 0.f;

    #pragma unroll
    for (int h = 0; h < 2; ++h) {
        const int t0 = h * HALF;

        // Phase A: 8 independent loads -> one long read burst.
        float4 xs[HALF];
        #pragma unroll
        for (int i = 0; i < HALF; ++i)
            xs[i] = xb[(t0 + i) * CHW4];

        // Phase B: scan + 8 stores -> one long write burst.
        float4 os[HALF];
        #pragma unroll
        for (int i = 0; i < HALF; ++i) {
            m0 = fmaf(w, m0, xs[i].x);
            m1 = fmaf(w, m1, xs[i].y);
            m2 = fmaf(w, m2, xs[i].z);
            m3 = fmaf(w, m3, xs[i].w);

            const float s0 = (m0 >= 1.0f) ? 1.0f : 0.0f;
            const float s1 = (m1 >= 1.0f) ? 1.0f : 0.0f;
            const float s2 = (m2 >= 1.0f) ? 1.0f : 0.0f;
            const float s3 = (m3 >= 1.0f) ? 1.0f : 0.0f;

            m0 = (s0 != 0.0f) ? 0.0f : m0;
            m1 = (s1 != 0.0f) ? 0.0f : m1;
            m2 = (s2 != 0.0f) ? 0.0f : m2;
            m3 = (s3 != 0.0f) ? 0.0f : m3;

            os[i].x = s0; os[i].y = s1; os[i].z = s2; os[i].w = s3;
        }

        #pragma unroll
        for (int i = 0; i < HALF; ++i)
            ob[(t0 + i) * CHW4] = os[i];
    }
}

extern "C" void kernel_launch(void* const* d_in, const int* in_sizes, int n_in,
                              void* d_out, int out_size)
{
    const float4* x  = (const float4*)d_in[0];
    const float*  wp = (const float*)d_in[1];
    float4* out = (float4*)d_out;

    const int blocks = (NV4 + TPB - 1) / TPB;   // 2048
    plif_kernel<<<blocks, TPB>>>(x, wp, out);
}